// round 17
// baseline (speedup 1.0000x reference)
#include <cuda_runtime.h>
#include <cstdint>

#define BATCH 2048
#define D0 256
#define D1 256
#define D2 256
#define D3 128

// Scratch (device globals: allocation-free per harness rules)
__device__ float g_We0[D1 * D0];
__device__ float g_We1[D2 * D1];
__device__ float g_W2h[D2 * D3];   // [k][o] hi tf32 part of We2^T (bit patterns)
__device__ float g_W2l[D2 * D3];   // [k][o] lo tf32 part
__device__ float g_h1[BATCH * D1];
__device__ float g_h2[BATCH * D2];

__device__ __forceinline__ float tanh_fast(float x) {
    float y;
    asm("tanh.approx.f32 %0, %1;" : "=f"(y) : "f"(x));
    return y;
}

__device__ __forceinline__ unsigned int to_tf32(float f) {
    unsigned int r;
    asm("cvt.rna.tf32.f32 %0, %1;" : "=r"(r) : "f"(f));
    return r;
}

__device__ __forceinline__ float atom_apply(float w, int idx) {
    float v = w;                       // identity
    if (idx == 1)      v = sinf(w);
    else if (idx == 2) v = tanhf(w);
    else if (idx == 3) v = w * w;
    return v;
}

// Precompute effective weights. We2 stored transposed + hi/lo tf32 split.
__global__ void prep_we_kernel(const float* __restrict__ W0, const int* __restrict__ f0,
                               const float* __restrict__ W1, const int* __restrict__ f1,
                               const float* __restrict__ W2, const int* __restrict__ f2) {
    const int n01 = D1 * D0;           // 65536
    const int n2  = D3 * D2;           // 32768
    const int stride = gridDim.x * blockDim.x;
    for (int t = blockIdx.x * blockDim.x + threadIdx.x; t < n01; t += stride) {
        g_We0[t] = atom_apply(W0[t], f0[t]);
        g_We1[t] = atom_apply(W1[t], f1[t]);
    }
    for (int t = blockIdx.x * blockDim.x + threadIdx.x; t < n2; t += stride) {
        int o = t >> 8;                // W2 is [128][256] row-major
        int k = t & 255;
        float v = atom_apply(W2[t], f2[t]);
        unsigned int hb = to_tf32(v);
        float hf = __uint_as_float(hb);
        unsigned int lb = to_tf32(v - hf);
        g_W2h[k * D3 + o] = __uint_as_float(hb);
        g_W2l[k * D3 + o] = __uint_as_float(lb);
    }
}

// Hidden layer: h_out[b,o] = sum_i tanh(h[b,i]*We[o,i]) + bias[o]
// MUFU-bound, measured at floor — unchanged.
template <int IN>
__global__ __launch_bounds__(256) void layer_tanh_kernel(
    const float* __restrict__ h_in,   // [BATCH, IN]
    const float* __restrict__ We,     // [OUT, IN]
    const float* __restrict__ bias,   // [OUT]
    float* __restrict__ h_out,        // [BATCH, OUT]
    int OUT) {
    __shared__ float We_s[IN][33];
    __shared__ float h_s[8][IN];

    const int tx = threadIdx.x;
    const int ty = threadIdx.y;
    const int tid = ty * 32 + tx;
    const int o0 = blockIdx.x * 32;
    const int b0 = blockIdx.y * 8;

    for (int idx = tid; idx < 32 * IN; idx += 256) {
        int o = idx / IN;
        int i = idx - o * IN;
        We_s[i][o] = We[(o0 + o) * IN + i];
    }
    const float4* Hg = reinterpret_cast<const float4*>(h_in + b0 * IN);
    float4* Hs = reinterpret_cast<float4*>(&h_s[0][0]);
    for (int idx = tid; idx < 8 * IN / 4; idx += 256) {
        Hs[idx] = Hg[idx];
    }
    __syncthreads();

    float acc0 = 0.f, acc1 = 0.f;
#pragma unroll 8
    for (int i = 0; i < IN; i += 2) {
        float z0 = h_s[ty][i]     * We_s[i][tx];
        float z1 = h_s[ty][i + 1] * We_s[i + 1][tx];
        acc0 += tanh_fast(z0);
        acc1 += tanh_fast(z1);
    }
    h_out[(b0 + ty) * OUT + o0 + tx] = acc0 + acc1 + bias[o0 + tx];
}

// Last layer on the tensor pipe, v2: tf32 split mma re-tiled for occupancy.
// CTA: 128 thr (4 warps), tile 32b x 32o, K=256. grid (64, 4) = 256 CTAs.
// h staged fp32 once (hi/lo split done in registers at fragment load);
// W hi/lo quarters staged from prep's pre-split arrays. smem 107 KB -> 2 CTA/SM.
#define HRS 260   // h smem row stride: frag bank (4*row + q + k0) -> 4g+q distinct
#define WRS 36    // W smem row stride: frag bank (4q + g + const) distinct
__global__ __launch_bounds__(128) void layer_lin_mma_kernel(
    const float* __restrict__ h_in,   // [BATCH, 256] fp32
    const float* __restrict__ W2h,    // [256][128] tf32-hi bits
    const float* __restrict__ W2l,    // [256][128] tf32-lo bits
    const float* __restrict__ bias,   // [128]
    float* __restrict__ out) {        // [BATCH, 128]
    constexpr int IN = D2;
    extern __shared__ float sh[];
    float* H_s  = sh;                      // [32][HRS] fp32   8320 floats
    float* Wh_s = sh + 32 * HRS;           // [256][WRS]       9216 floats
    float* Wl_s = sh + 32 * HRS + IN * WRS;// [256][WRS]       9216 floats

    const int tid = threadIdx.x;
    const int lane = tid & 31;
    const int w = tid >> 5;                // 0..3
    const int b0 = blockIdx.x * 32;
    const int obase = blockIdx.y * 32;     // this CTA's 32 output cols

    // Stage h tile [32][256] fp32 (LDG float4 coalesced; 16 per thread).
    for (int idx = tid; idx < 32 * IN / 4; idx += 128) {
        int b = idx >> 6;                  // /64
        int k4 = idx & 63;
        float4 v = *reinterpret_cast<const float4*>(&h_in[(b0 + b) * IN + k4 * 4]);
        *reinterpret_cast<float4*>(&H_s[b * HRS + k4 * 4]) = v;
    }
    // Stage W hi/lo quarters [256][32] (8 float4 cols per row).
    for (int idx = tid; idx < IN * 8; idx += 128) {
        int k = idx >> 3;
        int c4 = idx & 7;
        float4 vh = *reinterpret_cast<const float4*>(&W2h[k * D3 + obase + c4 * 4]);
        float4 vl = *reinterpret_cast<const float4*>(&W2l[k * D3 + obase + c4 * 4]);
        *reinterpret_cast<float4*>(&Wh_s[k * WRS + c4 * 4]) = vh;
        *reinterpret_cast<float4*>(&Wl_s[k * WRS + c4 * 4]) = vl;
    }
    __syncthreads();

    const int b_sub = (w & 1) * 16;
    const int o_sub = (w >> 1) * 16;
    const int g = lane >> 2;          // 0..7
    const int q = lane & 3;           // 0..3

    float d0[4] = {0.f, 0.f, 0.f, 0.f};   // o-tile 0 (cols o_sub..+7)
    float d1[4] = {0.f, 0.f, 0.f, 0.f};   // o-tile 1 (cols o_sub+8..+15)

    const float* HA = H_s + (b_sub + g) * HRS;       // row g
    const float* HB = H_s + (b_sub + g + 8) * HRS;   // row g+8

#pragma unroll 4
    for (int ks = 0; ks < IN / 8; ks++) {
        const int k0 = ks * 8;
        // A fragment fp32 loads (each LDS.32 conflict-free: banks 4g+q).
        float a0 = HA[k0 + q];
        float a1 = HB[k0 + q];
        float a2 = HA[k0 + q + 4];
        float a3 = HB[k0 + q + 4];
        // In-register tf32 hi/lo split (same arithmetic as R15's smem split).
        unsigned int ah0 = to_tf32(a0), ah1 = to_tf32(a1);
        unsigned int ah2 = to_tf32(a2), ah3 = to_tf32(a3);
        unsigned int al0 = to_tf32(a0 - __uint_as_float(ah0));
        unsigned int al1 = to_tf32(a1 - __uint_as_float(ah1));
        unsigned int al2 = to_tf32(a2 - __uint_as_float(ah2));
        unsigned int al3 = to_tf32(a3 - __uint_as_float(ah3));
        // B fragments, o-tile 0 (col o_sub+g) and o-tile 1 (col o_sub+8+g).
        unsigned int bh0 = __float_as_uint(Wh_s[(k0 + q) * WRS + o_sub + g]);
        unsigned int bh1 = __float_as_uint(Wh_s[(k0 + q + 4) * WRS + o_sub + g]);
        unsigned int bl0 = __float_as_uint(Wl_s[(k0 + q) * WRS + o_sub + g]);
        unsigned int bl1 = __float_as_uint(Wl_s[(k0 + q + 4) * WRS + o_sub + g]);
        unsigned int ch0 = __float_as_uint(Wh_s[(k0 + q) * WRS + o_sub + 8 + g]);
        unsigned int ch1 = __float_as_uint(Wh_s[(k0 + q + 4) * WRS + o_sub + 8 + g]);
        unsigned int cl0 = __float_as_uint(Wl_s[(k0 + q) * WRS + o_sub + 8 + g]);
        unsigned int cl1 = __float_as_uint(Wl_s[(k0 + q + 4) * WRS + o_sub + 8 + g]);

#define MMA(D, A0, A1, A2, A3, B0, B1)                                          \
        asm("mma.sync.aligned.m16n8k8.row.col.f32.tf32.tf32.f32 "               \
            "{%0,%1,%2,%3}, {%4,%5,%6,%7}, {%8,%9}, {%0,%1,%2,%3};"             \
            : "+f"(D[0]), "+f"(D[1]), "+f"(D[2]), "+f"(D[3])                    \
            : "r"(A0), "r"(A1), "r"(A2), "r"(A3), "r"(B0), "r"(B1))

        MMA(d0, ah0, ah1, ah2, ah3, bh0, bh1);
        MMA(d0, ah0, ah1, ah2, ah3, bl0, bl1);
        MMA(d0, al0, al1, al2, al3, bh0, bh1);
        MMA(d1, ah0, ah1, ah2, ah3, ch0, ch1);
        MMA(d1, ah0, ah1, ah2, ah3, cl0, cl1);
        MMA(d1, al0, al1, al2, al3, ch0, ch1);
#undef MMA
    }

    // Store: d[0],d[1] -> (row g, cols 2q,2q+1); d[2],d[3] -> row g+8.
    const int row0 = b0 + b_sub + g;
    const int c0 = obase + o_sub + 2 * q;
    const int c1 = c0 + 8;
    float2 bias0 = *reinterpret_cast<const float2*>(&bias[c0]);
    float2 bias1 = *reinterpret_cast<const float2*>(&bias[c1]);
    float2 v;
    v.x = d0[0] + bias0.x; v.y = d0[1] + bias0.y;
    *reinterpret_cast<float2*>(&out[row0 * D3 + c0]) = v;
    v.x = d0[2] + bias0.x; v.y = d0[3] + bias0.y;
    *reinterpret_cast<float2*>(&out[(row0 + 8) * D3 + c0]) = v;
    v.x = d1[0] + bias1.x; v.y = d1[1] + bias1.y;
    *reinterpret_cast<float2*>(&out[row0 * D3 + c1]) = v;
    v.x = d1[2] + bias1.x; v.y = d1[3] + bias1.y;
    *reinterpret_cast<float2*>(&out[(row0 + 8) * D3 + c1]) = v;
}

extern "C" void kernel_launch(void* const* d_in, const int* in_sizes, int n_in,
                              void* d_out, int out_size) {
    // Resolve input ordering at runtime (dict vs signature order).
    const float *x, *W0, *b0, *W1, *b1, *W2, *b2;
    const int *f0, *f1, *f2;
    x = (const float*)d_in[0];
    if (in_sizes[4] == 256) {
        // signature order: x, W0,b0, W1,b1, W2,b2, f0,f1,f2
        W0 = (const float*)d_in[1]; b0 = (const float*)d_in[2];
        W1 = (const float*)d_in[3]; b1 = (const float*)d_in[4];
        W2 = (const float*)d_in[5]; b2 = (const float*)d_in[6];
        f0 = (const int*)d_in[7];  f1 = (const int*)d_in[8];  f2 = (const int*)d_in[9];
    } else {
        // dict order: x, W0,b0,f0, W1,b1,f1, W2,b2,f2
        W0 = (const float*)d_in[1]; b0 = (const float*)d_in[2]; f0 = (const int*)d_in[3];
        W1 = (const float*)d_in[4]; b1 = (const float*)d_in[5]; f1 = (const int*)d_in[6];
        W2 = (const float*)d_in[7]; b2 = (const float*)d_in[8]; f2 = (const int*)d_in[9];
    }

    float *dWe0, *dWe1, *dW2h, *dW2l, *dh1, *dh2;
    cudaGetSymbolAddress((void**)&dWe0, g_We0);
    cudaGetSymbolAddress((void**)&dWe1, g_We1);
    cudaGetSymbolAddress((void**)&dW2h, g_W2h);
    cudaGetSymbolAddress((void**)&dW2l, g_W2l);
    cudaGetSymbolAddress((void**)&dh1, g_h1);
    cudaGetSymbolAddress((void**)&dh2, g_h2);

    float* out = (float*)d_out;

    // smem: (32*260 + 2*256*36) * 4 = 107,008 B -> 2 CTAs/SM.
    const int lin_smem = (32 * HRS + 2 * D2 * WRS) * (int)sizeof(float);
    cudaFuncSetAttribute(layer_lin_mma_kernel,
                         cudaFuncAttributeMaxDynamicSharedMemorySize, lin_smem);

    prep_we_kernel<<<256, 256>>>(W0, f0, W1, f1, W2, f2);

    dim3 blk(32, 8);
    // Layer 0: x -> h1 (MUFU tanh, at floor)
    layer_tanh_kernel<D0><<<dim3(D1 / 32, BATCH / 8), blk>>>(x, dWe0, b0, dh1, D1);
    // Layer 1: h1 -> h2 (MUFU tanh, at floor)
    layer_tanh_kernel<D1><<<dim3(D2 / 32, BATCH / 8), blk>>>(dh1, dWe1, b1, dh2, D2);
    // Layer 2: h2 -> out, tf32 split mma, grid 64x4 = 256 CTAs, 128 thr
    layer_lin_mma_kernel<<<dim3(BATCH / 32, 4), 128, lin_smem>>>(
        dh2, dW2h, dW2l, b2, out);
}